// round 5
// baseline (speedup 1.0000x reference)
#include <cuda_runtime.h>

#define MAXN 50000
#define MAXE 1000000

typedef unsigned long long u64;

// ---------------- scratch (device globals, no allocation) -------------------
__device__ __align__(16) float g_dinv[MAXN];
__device__ __align__(16) float g_buf1[MAXN * 128];   // A1, then A2
__device__ __align__(16) float g_buf2[MAXN * 128];   // T2
__device__ int g_cnt[MAXN];     // in-degree (excl self-loop)
__device__ int g_off[MAXN];     // CSR offsets
__device__ int g_pos[MAXN];     // scatter cursors
__device__ int g_srt[MAXE];     // src indices sorted by dst

// ---------------- f32x2 helpers (Blackwell packed fp32) ---------------------
__device__ __forceinline__ u64 fma2(u64 a, u64 b, u64 c) {
    u64 d; asm("fma.rn.f32x2 %0, %1, %2, %3;" : "=l"(d) : "l"(a), "l"(b), "l"(c));
    return d;
}
__device__ __forceinline__ u64 pack2(float lo, float hi) {
    u64 d; asm("mov.b64 %0, {%1, %2};" : "=l"(d) : "f"(lo), "f"(hi));
    return d;
}
__device__ __forceinline__ void unpack2(u64 v, float& lo, float& hi) {
    asm("mov.b64 {%0, %1}, %2;" : "=f"(lo), "=f"(hi) : "l"(v));
}
__device__ __forceinline__ float leaky(float v) { return v >= 0.f ? v : 0.01f * v; }

// ---------------- CSR build --------------------------------------------------
__global__ void k_zero(int n) {
    int i = blockIdx.x * blockDim.x + threadIdx.x;
    if (i < n) g_cnt[i] = 0;
}

__global__ void k_hist(const int* __restrict__ ei, int E) {
    int i = blockIdx.x * blockDim.x + threadIdx.x;
    if (i < E) atomicAdd(&g_cnt[ei[E + i]], 1);
}

// single block, 1024 threads: exclusive scan of g_cnt -> g_off, g_pos; dinv too
__global__ void __launch_bounds__(1024) k_scan(int n) {
    __shared__ int tmp[1024];
    int tid = threadIdx.x;
    int chunk = (n + 1023) >> 10;
    int start = tid * chunk;
    int end = start + chunk; if (end > n) end = n;
    int s = 0;
    for (int i = start; i < end; i++) s += g_cnt[i];
    tmp[tid] = s;
    __syncthreads();
    for (int off = 1; off < 1024; off <<= 1) {
        int v = (tid >= off) ? tmp[tid - off] : 0;
        __syncthreads();
        tmp[tid] += v;
        __syncthreads();
    }
    int base = tmp[tid] - s;  // exclusive prefix
    for (int i = start; i < end; i++) {
        g_off[i] = base;
        g_pos[i] = base;
        base += g_cnt[i];
        g_dinv[i] = rsqrtf((float)(g_cnt[i] + 1));  // +1 self-loop
    }
}

__global__ void k_scatter(const int* __restrict__ ei, int E) {
    int i = blockIdx.x * blockDim.x + threadIdx.x;
    if (i >= E) return;
    int d = ei[E + i];
    int p = atomicAdd(&g_pos[d], 1);
    g_srt[p] = ei[i];
}

// ---------------- pull aggregation: warp per dst node ------------------------
// out[d] = dinv[d] * ( sum_{s in N(d)} dinv[s]*in[s] + dinv[d]*in[d] )
__global__ void __launch_bounds__(256) k_pull(const float* __restrict__ xin,
                                              int pass, int n) {
    int node = (blockIdx.x * blockDim.x + threadIdx.x) >> 5;
    int lane = threadIdx.x & 31;
    if (node >= n) return;
    const float* in = pass ? g_buf2 : xin;
    int off = g_off[node], cnt = g_cnt[node];
    float dd = g_dinv[node];

    float4 v = reinterpret_cast<const float4*>(in + (size_t)node * 128)[lane];
    float4 acc;
    acc.x = dd * v.x; acc.y = dd * v.y; acc.z = dd * v.z; acc.w = dd * v.w;

    int j = 0;
    for (; j + 1 < cnt; j += 2) {
        int s0 = g_srt[off + j], s1 = g_srt[off + j + 1];
        float w0 = g_dinv[s0], w1 = g_dinv[s1];
        float4 a = reinterpret_cast<const float4*>(in + (size_t)s0 * 128)[lane];
        float4 b = reinterpret_cast<const float4*>(in + (size_t)s1 * 128)[lane];
        acc.x += w0 * a.x + w1 * b.x;  acc.y += w0 * a.y + w1 * b.y;
        acc.z += w0 * a.z + w1 * b.z;  acc.w += w0 * a.w + w1 * b.w;
    }
    if (j < cnt) {
        int s0 = g_srt[off + j];
        float w0 = g_dinv[s0];
        float4 a = reinterpret_cast<const float4*>(in + (size_t)s0 * 128)[lane];
        acc.x += w0 * a.x; acc.y += w0 * a.y; acc.z += w0 * a.z; acc.w += w0 * a.w;
    }
    acc.x *= dd; acc.y *= dd; acc.z *= dd; acc.w *= dd;
    reinterpret_cast<float4*>(g_buf1 + (size_t)node * 128)[lane] = acc;
}

// ---------------- fused GEMM: H1 = leaky(A1@W1+b1); T2 = H1@W3 --------------
// BM=32 rows/block, 256 threads. f32x2 packed row-pairs.
// smem: A2[128][16] u64 (k, pair)  +  H2[512][18] u64 (j, pair)
__global__ void __launch_bounds__(256) k_gemm12(const float* __restrict__ W1,
                                                const float* __restrict__ b1,
                                                const float* __restrict__ W3,
                                                int n) {
    extern __shared__ u64 sm[];
    u64* A2 = sm;                 // idx k*16 + p
    u64* H2 = sm + 128 * 16;      // idx j*18 + p
    float* A2f = (float*)A2;

    int tid = threadIdx.x;
    int base = blockIdx.x * 32;
    int valid = n - base; if (valid > 32) valid = 32;

    // load + repack A-tile: (row m, f4-col c) -> packed (k, pair=m/2, half=m&1)
    for (int idx = tid; idx < 32 * 32; idx += 256) {
        int m = idx & 31, c = idx >> 5;
        float4 v = make_float4(0.f, 0.f, 0.f, 0.f);
        if (m < valid)
            v = reinterpret_cast<const float4*>(g_buf1 + (size_t)(base + m) * 128)[c];
        int p = m >> 1, h = m & 1;
        int k0 = c * 4;
        A2f[((k0 + 0) * 16 + p) * 2 + h] = v.x;
        A2f[((k0 + 1) * 16 + p) * 2 + h] = v.y;
        A2f[((k0 + 2) * 16 + p) * 2 + h] = v.z;
        A2f[((k0 + 3) * 16 + p) * 2 + h] = v.w;
    }
    __syncthreads();

    // Phase 1: thread j -> H1 columns j and j+256, 16 row-pairs
    {
        int j = tid;
        u64 acc0[16], acc1[16];
#pragma unroll
        for (int p = 0; p < 16; p++) { acc0[p] = 0ull; acc1[p] = 0ull; }

#pragma unroll 2
        for (int k = 0; k < 128; k++) {
            float w0 = W1[(size_t)k * 512 + j];
            float w1 = W1[(size_t)k * 512 + j + 256];
            u64 W0 = pack2(w0, w0), W1p = pack2(w1, w1);
            const ulonglong2* row = reinterpret_cast<const ulonglong2*>(A2 + k * 16);
#pragma unroll
            for (int q = 0; q < 8; q++) {
                ulonglong2 t = row[q];
                acc0[2 * q]     = fma2(t.x, W0, acc0[2 * q]);
                acc1[2 * q]     = fma2(t.x, W1p, acc1[2 * q]);
                acc0[2 * q + 1] = fma2(t.y, W0, acc0[2 * q + 1]);
                acc1[2 * q + 1] = fma2(t.y, W1p, acc1[2 * q + 1]);
            }
        }
        float bb0 = b1[j], bb1 = b1[j + 256];
#pragma unroll
        for (int p = 0; p < 16; p++) {
            float lo, hi;
            unpack2(acc0[p], lo, hi);
            H2[(size_t)j * 18 + p] = pack2(leaky(lo + bb0), leaky(hi + bb0));
            unpack2(acc1[p], lo, hi);
            H2[(size_t)(j + 256) * 18 + p] = pack2(leaky(lo + bb1), leaky(hi + bb1));
        }
    }
    __syncthreads();

    // Phase 2: T2 = H1 @ W3. thread -> col jc, 8 row-pairs (group g)
    {
        int jc = tid & 127;
        int g = tid >> 7;  // 0/1 -> pairs 8g..8g+7
        u64 acc[8];
#pragma unroll
        for (int p = 0; p < 8; p++) acc[p] = 0ull;

#pragma unroll 2
        for (int k = 0; k < 512; k++) {
            float w = W3[(size_t)k * 128 + jc];
            u64 W = pack2(w, w);
            const ulonglong2* row =
                reinterpret_cast<const ulonglong2*>(H2 + (size_t)k * 18 + g * 8);
#pragma unroll
            for (int q = 0; q < 4; q++) {
                ulonglong2 t = row[q];
                acc[2 * q]     = fma2(t.x, W, acc[2 * q]);
                acc[2 * q + 1] = fma2(t.y, W, acc[2 * q + 1]);
            }
        }
#pragma unroll
        for (int p = 0; p < 8; p++) {
            int pr = g * 8 + p;
            float lo, hi;
            unpack2(acc[p], lo, hi);
            int r0 = 2 * pr, r1 = 2 * pr + 1;
            if (r0 < valid) g_buf2[(size_t)(base + r0) * 128 + jc] = lo;
            if (r1 < valid) g_buf2[(size_t)(base + r1) * 128 + jc] = hi;
        }
    }
}

// ---------------- head: leaky(A2+b3) -> FC1+leaky -> FC2 --------------------
__global__ void __launch_bounds__(256) k_final(
    const float* __restrict__ b3,
    const float* __restrict__ fc1w, const float* __restrict__ fc1b,
    const float* __restrict__ fc2w, const float* __restrict__ fc2b,
    float* __restrict__ out, int n) {
    __shared__ u64 A2[128 * 16];     // (k, pair)
    __shared__ float red[32][8];
    float* A2f = (float*)A2;

    int tid = threadIdx.x;
    int base = blockIdx.x * 32;
    int valid = n - base; if (valid > 32) valid = 32;

    // load + repack with bias b3 + leaky fused
    for (int idx = tid; idx < 32 * 32; idx += 256) {
        int m = idx & 31, c = idx >> 5;
        float4 v = make_float4(0.f, 0.f, 0.f, 0.f);
        if (m < valid)
            v = reinterpret_cast<const float4*>(g_buf1 + (size_t)(base + m) * 128)[c];
        float4 bb = reinterpret_cast<const float4*>(b3)[c];
        v.x = leaky(v.x + bb.x); v.y = leaky(v.y + bb.y);
        v.z = leaky(v.z + bb.z); v.w = leaky(v.w + bb.w);
        int p = m >> 1, h = m & 1;
        int k0 = c * 4;
        A2f[((k0 + 0) * 16 + p) * 2 + h] = v.x;
        A2f[((k0 + 1) * 16 + p) * 2 + h] = v.y;
        A2f[((k0 + 2) * 16 + p) * 2 + h] = v.z;
        A2f[((k0 + 3) * 16 + p) * 2 + h] = v.w;
    }
    __syncthreads();

    int j = tid;  // FC1 output channel
    u64 acc[16];
#pragma unroll
    for (int p = 0; p < 16; p++) acc[p] = 0ull;

    for (int k4 = 0; k4 < 32; k4++) {
        float4 w4 = reinterpret_cast<const float4*>(fc1w + (size_t)j * 128)[k4];
        u64 W[4] = { pack2(w4.x, w4.x), pack2(w4.y, w4.y),
                     pack2(w4.z, w4.z), pack2(w4.w, w4.w) };
#pragma unroll
        for (int kk = 0; kk < 4; kk++) {
            const ulonglong2* row =
                reinterpret_cast<const ulonglong2*>(A2 + (k4 * 4 + kk) * 16);
#pragma unroll
            for (int q = 0; q < 8; q++) {
                ulonglong2 t = row[q];
                acc[2 * q]     = fma2(t.x, W[kk], acc[2 * q]);
                acc[2 * q + 1] = fma2(t.y, W[kk], acc[2 * q + 1]);
            }
        }
    }

    // unpack to 32 per-row values, FC1 bias+leaky, *fc2w[j], reduce over j
    float acc32[32];
#pragma unroll
    for (int p = 0; p < 16; p++) unpack2(acc[p], acc32[2 * p], acc32[2 * p + 1]);

    float fb = fc1b[j], w2 = fc2w[j];
    int lane = tid & 31, wid = tid >> 5;
#pragma unroll
    for (int m = 0; m < 32; m++) {
        float v = leaky(acc32[m] + fb) * w2;
#pragma unroll
        for (int off = 16; off; off >>= 1)
            v += __shfl_xor_sync(0xffffffffu, v, off);
        if (lane == 0) red[m][wid] = v;
    }
    __syncthreads();

    if (tid < 32 && tid < valid) {
        float s = fc2b[0];
#pragma unroll
        for (int w = 0; w < 8; w++) s += red[tid][w];
        out[base + tid] = s;
    }
}

// ---------------------------------------------------------------------------
extern "C" void kernel_launch(void* const* d_in, const int* in_sizes, int n_in,
                              void* d_out, int out_size) {
    const float* x    = (const float*)d_in[0];
    const int*   ei   = (const int*)d_in[1];   // int32 (JAX x64 disabled)
    const float* W1   = (const float*)d_in[2];
    const float* b1   = (const float*)d_in[3];
    const float* W3   = (const float*)d_in[4];
    const float* b3   = (const float*)d_in[5];
    const float* fc1w = (const float*)d_in[6];
    const float* fc1b = (const float*)d_in[7];
    const float* fc2w = (const float*)d_in[8];
    const float* fc2b = (const float*)d_in[9];
    float* out = (float*)d_out;

    int n = in_sizes[0] / 128;
    int E = in_sizes[1] / 2;

    static int smem_set = 0;
    const int smem_gemm = (128 * 16 + 512 * 18) * (int)sizeof(u64);  // 90112 B
    if (!smem_set) {
        cudaFuncSetAttribute(k_gemm12, cudaFuncAttributeMaxDynamicSharedMemorySize,
                             smem_gemm);
        smem_set = 1;
    }

    // CSR build (once; reused by both aggregation passes)
    k_zero<<<(n + 255) / 256, 256>>>(n);
    k_hist<<<(E + 255) / 256, 256>>>(ei, E);
    k_scan<<<1, 1024>>>(n);
    k_scatter<<<(E + 255) / 256, 256>>>(ei, E);

    // A1 = Ahat @ x   -> g_buf1
    k_pull<<<(n * 32 + 255) / 256, 256>>>(x, 0, n);
    // T2 = leaky(A1@W1+b1) @ W3   -> g_buf2
    k_gemm12<<<(n + 31) / 32, 256, smem_gemm>>>(W1, b1, W3, n);
    // A2 = Ahat @ T2   -> g_buf1
    k_pull<<<(n * 32 + 255) / 256, 256>>>(x, 1, n);
    // head
    k_final<<<(n + 31) / 32, 256>>>(b3, fc1w, fc1b, fc2w, fc2b, out, n);
}

// round 6
// speedup vs baseline: 1.1305x; 1.1305x over previous
#include <cuda_runtime.h>

#define MAXN 50000
#define MAXE 1000000

typedef unsigned long long u64;

// ---------------- scratch (device globals, no allocation) -------------------
__device__ __align__(16) float g_dinv[MAXN];
__device__ __align__(16) float g_buf1[MAXN * 128];   // A1, then A2
__device__ __align__(16) float g_buf2[MAXN * 128];   // T2
__device__ int g_cnt[MAXN];     // in-degree (excl self-loop)
__device__ int g_off[MAXN];     // CSR offsets
__device__ int g_pos[MAXN];     // scatter cursors
__device__ int g_srt[MAXE];     // src indices sorted by dst

// ---------------- f32x2 helpers (Blackwell packed fp32) ---------------------
__device__ __forceinline__ u64 fma2(u64 a, u64 b, u64 c) {
    u64 d; asm("fma.rn.f32x2 %0, %1, %2, %3;" : "=l"(d) : "l"(a), "l"(b), "l"(c));
    return d;
}
__device__ __forceinline__ u64 pack2(float lo, float hi) {
    u64 d; asm("mov.b64 %0, {%1, %2};" : "=l"(d) : "f"(lo), "f"(hi));
    return d;
}
__device__ __forceinline__ void unpack2(u64 v, float& lo, float& hi) {
    asm("mov.b64 {%0, %1}, %2;" : "=f"(lo), "=f"(hi) : "l"(v));
}
__device__ __forceinline__ float leaky(float v) { return v >= 0.f ? v : 0.01f * v; }

// ---------------- CSR build --------------------------------------------------
__global__ void k_zero(int n) {
    int i = blockIdx.x * blockDim.x + threadIdx.x;
    if (i < n) g_cnt[i] = 0;
}

__global__ void k_hist(const int* __restrict__ ei, int E) {
    int i = blockIdx.x * blockDim.x + threadIdx.x;
    if (i < E) atomicAdd(&g_cnt[ei[E + i]], 1);
}

// single block, 1024 threads: exclusive scan of g_cnt -> g_off, g_pos; dinv too
__global__ void __launch_bounds__(1024) k_scan(int n) {
    __shared__ int tmp[1024];
    int tid = threadIdx.x;
    int chunk = (n + 1023) >> 10;
    int start = tid * chunk;
    int end = start + chunk; if (end > n) end = n;
    int s = 0;
    for (int i = start; i < end; i++) s += g_cnt[i];
    tmp[tid] = s;
    __syncthreads();
    for (int off = 1; off < 1024; off <<= 1) {
        int v = (tid >= off) ? tmp[tid - off] : 0;
        __syncthreads();
        tmp[tid] += v;
        __syncthreads();
    }
    int base = tmp[tid] - s;  // exclusive prefix
    for (int i = start; i < end; i++) {
        g_off[i] = base;
        g_pos[i] = base;
        base += g_cnt[i];
        g_dinv[i] = rsqrtf((float)(g_cnt[i] + 1));  // +1 self-loop
    }
}

__global__ void k_scatter(const int* __restrict__ ei, int E) {
    int i = blockIdx.x * blockDim.x + threadIdx.x;
    if (i >= E) return;
    int d = ei[E + i];
    int p = atomicAdd(&g_pos[d], 1);
    g_srt[p] = ei[i];
}

// ---------------- pull aggregation: warp per dst node ------------------------
// out[d] = dinv[d] * ( sum_{s in N(d)} dinv[s]*in[s] + dinv[d]*in[d] )
__global__ void __launch_bounds__(256) k_pull(const float* __restrict__ xin,
                                              int pass, int n) {
    int node = (blockIdx.x * blockDim.x + threadIdx.x) >> 5;
    int lane = threadIdx.x & 31;
    if (node >= n) return;
    const float* in = pass ? g_buf2 : xin;
    int off = g_off[node], cnt = g_cnt[node];
    float dd = g_dinv[node];

    float4 v = reinterpret_cast<const float4*>(in + (size_t)node * 128)[lane];
    float4 acc;
    acc.x = dd * v.x; acc.y = dd * v.y; acc.z = dd * v.z; acc.w = dd * v.w;

    int j = 0;
    for (; j + 3 < cnt; j += 4) {
        int s0 = g_srt[off + j],     s1 = g_srt[off + j + 1];
        int s2 = g_srt[off + j + 2], s3 = g_srt[off + j + 3];
        float w0 = g_dinv[s0], w1 = g_dinv[s1];
        float w2 = g_dinv[s2], w3 = g_dinv[s3];
        float4 a = reinterpret_cast<const float4*>(in + (size_t)s0 * 128)[lane];
        float4 b = reinterpret_cast<const float4*>(in + (size_t)s1 * 128)[lane];
        float4 c = reinterpret_cast<const float4*>(in + (size_t)s2 * 128)[lane];
        float4 e = reinterpret_cast<const float4*>(in + (size_t)s3 * 128)[lane];
        acc.x += w0 * a.x + w1 * b.x + w2 * c.x + w3 * e.x;
        acc.y += w0 * a.y + w1 * b.y + w2 * c.y + w3 * e.y;
        acc.z += w0 * a.z + w1 * b.z + w2 * c.z + w3 * e.z;
        acc.w += w0 * a.w + w1 * b.w + w2 * c.w + w3 * e.w;
    }
    for (; j < cnt; j++) {
        int s0 = g_srt[off + j];
        float w0 = g_dinv[s0];
        float4 a = reinterpret_cast<const float4*>(in + (size_t)s0 * 128)[lane];
        acc.x += w0 * a.x; acc.y += w0 * a.y; acc.z += w0 * a.z; acc.w += w0 * a.w;
    }
    acc.x *= dd; acc.y *= dd; acc.z *= dd; acc.w *= dd;
    reinterpret_cast<float4*>(g_buf1 + (size_t)node * 128)[lane] = acc;
}

// ---------------- fused GEMM: H1 = leaky(A1@W1+b1); T2 = H1@W3 --------------
// BM=16 rows/block (8 row-pairs), 256 threads. f32x2 packed.
// smem: A2[128][8] u64 (k, pair) = 8 KB ; H2[512][10] u64 (j, pair<8) = 40 KB
__global__ void __launch_bounds__(256) k_gemm12(const float* __restrict__ W1,
                                                const float* __restrict__ b1,
                                                const float* __restrict__ W3,
                                                int n) {
    __shared__ u64 A2[128 * 8];
    __shared__ u64 H2[512 * 10];   // stride 10 keeps 16B alignment for u64x2
    float* A2f = (float*)A2;

    int tid = threadIdx.x;
    int base = blockIdx.x * 16;
    int valid = n - base; if (valid > 16) valid = 16;

    // load + repack A-tile: (row m, f4-col c) -> (k, pair=m/2, half=m&1)
    for (int idx = tid; idx < 16 * 32; idx += 256) {
        int m = idx & 15, c = idx >> 4;
        float4 v = make_float4(0.f, 0.f, 0.f, 0.f);
        if (m < valid)
            v = reinterpret_cast<const float4*>(g_buf1 + (size_t)(base + m) * 128)[c];
        int p = m >> 1, h = m & 1;
        int k0 = c * 4;
        A2f[((k0 + 0) * 8 + p) * 2 + h] = v.x;
        A2f[((k0 + 1) * 8 + p) * 2 + h] = v.y;
        A2f[((k0 + 2) * 8 + p) * 2 + h] = v.z;
        A2f[((k0 + 3) * 8 + p) * 2 + h] = v.w;
    }
    __syncthreads();

    // Phase 1: thread j -> H1 columns j and j+256, 8 row-pairs
    {
        int j = tid;
        u64 acc0[8], acc1[8];
#pragma unroll
        for (int p = 0; p < 8; p++) { acc0[p] = 0ull; acc1[p] = 0ull; }

#pragma unroll 4
        for (int k = 0; k < 128; k++) {
            float w0 = W1[(size_t)k * 512 + j];
            float w1 = W1[(size_t)k * 512 + j + 256];
            u64 W0 = pack2(w0, w0), W1p = pack2(w1, w1);
            const ulonglong2* row = reinterpret_cast<const ulonglong2*>(A2 + k * 8);
#pragma unroll
            for (int q = 0; q < 4; q++) {
                ulonglong2 t = row[q];
                acc0[2 * q]     = fma2(t.x, W0, acc0[2 * q]);
                acc1[2 * q]     = fma2(t.x, W1p, acc1[2 * q]);
                acc0[2 * q + 1] = fma2(t.y, W0, acc0[2 * q + 1]);
                acc1[2 * q + 1] = fma2(t.y, W1p, acc1[2 * q + 1]);
            }
        }
        float bb0 = b1[j], bb1 = b1[j + 256];
#pragma unroll
        for (int p = 0; p < 8; p++) {
            float lo, hi;
            unpack2(acc0[p], lo, hi);
            H2[(size_t)j * 10 + p] = pack2(leaky(lo + bb0), leaky(hi + bb0));
            unpack2(acc1[p], lo, hi);
            H2[(size_t)(j + 256) * 10 + p] = pack2(leaky(lo + bb1), leaky(hi + bb1));
        }
    }
    __syncthreads();

    // Phase 2: T2 = H1 @ W3. thread -> col jc = tid&127, 4 row-pairs (group g)
    {
        int jc = tid & 127;
        int g = tid >> 7;  // 0/1 -> pairs 4g..4g+3
        u64 acc[4];
#pragma unroll
        for (int p = 0; p < 4; p++) acc[p] = 0ull;

#pragma unroll 4
        for (int k = 0; k < 512; k++) {
            float w = W3[(size_t)k * 128 + jc];
            u64 W = pack2(w, w);
            const ulonglong2* row =
                reinterpret_cast<const ulonglong2*>(H2 + (size_t)k * 10 + g * 4);
#pragma unroll
            for (int q = 0; q < 2; q++) {
                ulonglong2 t = row[q];
                acc[2 * q]     = fma2(t.x, W, acc[2 * q]);
                acc[2 * q + 1] = fma2(t.y, W, acc[2 * q + 1]);
            }
        }
#pragma unroll
        for (int p = 0; p < 4; p++) {
            int pr = g * 4 + p;
            float lo, hi;
            unpack2(acc[p], lo, hi);
            int r0 = 2 * pr, r1 = 2 * pr + 1;
            if (r0 < valid) g_buf2[(size_t)(base + r0) * 128 + jc] = lo;
            if (r1 < valid) g_buf2[(size_t)(base + r1) * 128 + jc] = hi;
        }
    }
}

// ---------------- head (R4-proven scalar version) ----------------------------
__global__ void __launch_bounds__(256) k_final(
    const float* __restrict__ b3,
    const float* __restrict__ fc1w, const float* __restrict__ fc1b,
    const float* __restrict__ fc2w, const float* __restrict__ fc2b,
    float* __restrict__ out, int n) {
    __shared__ float h2s[32][128];
    __shared__ float red[32][8];

    int tid = threadIdx.x;
    int base = blockIdx.x * 32;
    int valid = n - base; if (valid > 32) valid = 32;

    for (int idx = tid; idx < 32 * 32; idx += 256) {
        int m = idx >> 5, c = idx & 31;
        float4 v = make_float4(0.f, 0.f, 0.f, 0.f);
        if (m < valid)
            v = reinterpret_cast<const float4*>(g_buf1 + (size_t)(base + m) * 128)[c];
        float4 bb = reinterpret_cast<const float4*>(b3)[c];
        v.x = leaky(v.x + bb.x); v.y = leaky(v.y + bb.y);
        v.z = leaky(v.z + bb.z); v.w = leaky(v.w + bb.w);
        reinterpret_cast<float4*>(&h2s[m][0])[c] = v;
    }
    __syncthreads();

    int j = tid;  // FC1 output channel
    float acc[32];
#pragma unroll
    for (int m = 0; m < 32; m++) acc[m] = 0.f;

    for (int k4 = 0; k4 < 32; k4++) {
        float4 w = reinterpret_cast<const float4*>(fc1w + (size_t)j * 128)[k4];
#pragma unroll
        for (int m = 0; m < 32; m++) {
            float4 h = reinterpret_cast<const float4*>(&h2s[m][0])[k4];
            acc[m] += h.x * w.x; acc[m] += h.y * w.y;
            acc[m] += h.z * w.z; acc[m] += h.w * w.w;
        }
    }

    float fb = fc1b[j], w2 = fc2w[j];
    int lane = tid & 31, wid = tid >> 5;
#pragma unroll
    for (int m = 0; m < 32; m++) {
        float v = leaky(acc[m] + fb) * w2;
#pragma unroll
        for (int off = 16; off; off >>= 1)
            v += __shfl_xor_sync(0xffffffffu, v, off);
        if (lane == 0) red[m][wid] = v;
    }
    __syncthreads();

    if (tid < 32 && tid < valid) {
        float s = fc2b[0];
#pragma unroll
        for (int w = 0; w < 8; w++) s += red[tid][w];
        out[base + tid] = s;
    }
}

// ---------------------------------------------------------------------------
extern "C" void kernel_launch(void* const* d_in, const int* in_sizes, int n_in,
                              void* d_out, int out_size) {
    const float* x    = (const float*)d_in[0];
    const int*   ei   = (const int*)d_in[1];   // int32 (JAX x64 disabled)
    const float* W1   = (const float*)d_in[2];
    const float* b1   = (const float*)d_in[3];
    const float* W3   = (const float*)d_in[4];
    const float* b3   = (const float*)d_in[5];
    const float* fc1w = (const float*)d_in[6];
    const float* fc1b = (const float*)d_in[7];
    const float* fc2w = (const float*)d_in[8];
    const float* fc2b = (const float*)d_in[9];
    float* out = (float*)d_out;

    int n = in_sizes[0] / 128;
    int E = in_sizes[1] / 2;

    // CSR build (once; reused by both aggregation passes)
    k_zero<<<(n + 255) / 256, 256>>>(n);
    k_hist<<<(E + 255) / 256, 256>>>(ei, E);
    k_scan<<<1, 1024>>>(n);
    k_scatter<<<(E + 255) / 256, 256>>>(ei, E);

    // A1 = Ahat @ x   -> g_buf1
    k_pull<<<(n * 32 + 255) / 256, 256>>>(x, 0, n);
    // T2 = leaky(A1@W1+b1) @ W3   -> g_buf2
    k_gemm12<<<(n + 15) / 16, 256>>>(W1, b1, W3, n);
    // A2 = Ahat @ T2   -> g_buf1
    k_pull<<<(n * 32 + 255) / 256, 256>>>(x, 1, n);
    // head
    k_final<<<(n + 31) / 32, 256>>>(b3, fc1w, fc1b, fc2w, fc2b, out, n);
}